// round 1
// baseline (speedup 1.0000x reference)
#include <cuda_runtime.h>
#include <math_constants.h>

// Problem constants
#define B_    64
#define J_    8
#define D_    256
#define NEG_  2048          // K*M = 64*32
#define SPLIT_ 16           // blocks per batch in neg_kernel
#define NPB_  (NEG_/SPLIT_) // 128 negatives per block
#define INV_TEMP 10.0f
#define EPS_  1e-8f

// Scratch: per-block (m, s) logsumexp partials. No allocation allowed -> device global.
__device__ float g_partials[B_ * SPLIT_ * 2];

__device__ __forceinline__ void lse_comb(float& m, float& s, float m2, float s2) {
    float M = fmaxf(m, m2);
    if (M == -CUDART_INF_F) { m = -CUDART_INF_F; s = 0.0f; return; }
    s = s * __expf(m - M) + s2 * __expf(m2 - M);
    m = M;
}

// ---------------------------------------------------------------------------
// Kernel 1: per-(batch, chunk) masked online logsumexp over negatives.
// Only negatives whose label matches the batch label are loaded/computed.
// ---------------------------------------------------------------------------
__global__ __launch_bounds__(512) void neg_kernel(
    const float* __restrict__ childrens,      // (B, J, D)
    const float* __restrict__ negs,           // (B, NEG, D)
    const int*   __restrict__ labels,         // (B, J)
    const int*   __restrict__ neg_labels)     // (B, NEG)
{
    const int b     = blockIdx.x >> 4;        // / SPLIT_
    const int chunk = blockIdx.x & (SPLIT_ - 1);
    const int tid   = threadIdx.x;
    const int warp  = tid >> 5;
    const int lane  = tid & 31;

    __shared__ float s_child[D_];
    __shared__ float s_invcn;
    __shared__ float s_m[16], s_s[16];

    // Load child vector (last J slot) into shared memory.
    const float* childp = childrens + ((size_t)b * J_ + (J_ - 1)) * D_;
    if (tid < 64) ((float4*)s_child)[tid] = ((const float4*)childp)[tid];
    __syncthreads();

    // Warp 0: child squared-norm -> 1/max(||child||, eps)
    if (warp == 0) {
        float ss = 0.0f;
        #pragma unroll
        for (int i = 0; i < 8; i++) { float v = s_child[lane + i * 32]; ss += v * v; }
        #pragma unroll
        for (int o = 16; o; o >>= 1) ss += __shfl_xor_sync(0xffffffffu, ss, o);
        if (lane == 0) s_invcn = 1.0f / fmaxf(sqrtf(ss), EPS_);
    }
    __syncthreads();

    const int label = __ldg(labels + b * J_ + (J_ - 1));
    const float invcn = s_invcn;

    const float* negbase = negs + (size_t)b * NEG_ * D_;
    const int*   nl      = neg_labels + (size_t)b * NEG_;
    const int    nbase   = chunk * NPB_ + warp * 8;

    // Prefetch this warp's 8 labels (independent loads, good MLP).
    int lab[8];
    #pragma unroll
    for (int i = 0; i < 8; i++) lab[i] = __ldg(nl + nbase + i);

    // Per-warp online logsumexp over matching negatives.
    float m = -CUDART_INF_F, s = 0.0f;
    const float c0 = s_child[lane * 4 + 0];
    const float c1 = s_child[lane * 4 + 1];
    const float c2 = s_child[lane * 4 + 2];
    const float c3 = s_child[lane * 4 + 3];
    const float c4 = s_child[128 + lane * 4 + 0];
    const float c5 = s_child[128 + lane * 4 + 1];
    const float c6 = s_child[128 + lane * 4 + 2];
    const float c7 = s_child[128 + lane * 4 + 3];

    #pragma unroll
    for (int i = 0; i < 8; i++) {
        if (lab[i] == label) {
            const float4* p = (const float4*)(negbase + (size_t)(nbase + i) * D_);
            float4 a = p[lane];
            float4 c = p[lane + 32];
            float dot = a.x * c0 + a.y * c1 + a.z * c2 + a.w * c3
                      + c.x * c4 + c.y * c5 + c.z * c6 + c.w * c7;
            float ss  = a.x * a.x + a.y * a.y + a.z * a.z + a.w * a.w
                      + c.x * c.x + c.y * c.y + c.z * c.z + c.w * c.w;
            #pragma unroll
            for (int o = 16; o; o >>= 1) {
                dot += __shfl_xor_sync(0xffffffffu, dot, o);
                ss  += __shfl_xor_sync(0xffffffffu, ss,  o);
            }
            float sim = dot * invcn / fmaxf(sqrtf(ss), EPS_) * INV_TEMP;
            float M2  = fmaxf(m, sim);
            s = s * __expf(m - M2) + __expf(sim - M2);
            m = M2;
        }
    }

    if (lane == 0) { s_m[warp] = m; s_s[warp] = s; }
    __syncthreads();

    // Warp 0 combines the 16 warp partials and writes the block partial.
    if (warp == 0) {
        float mm = (lane < 16) ? s_m[lane] : -CUDART_INF_F;
        float sv = (lane < 16) ? s_s[lane] : 0.0f;
        #pragma unroll
        for (int o = 16; o; o >>= 1) {
            float m2 = __shfl_xor_sync(0xffffffffu, mm, o);
            float s2 = __shfl_xor_sync(0xffffffffu, sv, o);
            lse_comb(mm, sv, m2, s2);
        }
        if (lane == 0) {
            g_partials[blockIdx.x * 2 + 0] = mm;
            g_partials[blockIdx.x * 2 + 1] = sv;
        }
    }
}

// ---------------------------------------------------------------------------
// Kernel 2: per-batch pos_sim + fold partials + final deterministic sum.
// One block, 32 warps; each warp handles 2 batches.
// ---------------------------------------------------------------------------
__global__ __launch_bounds__(1024) void final_kernel(
    const float* __restrict__ childrens,      // (B, J, D)
    const float* __restrict__ pos,            // (B, J, D)
    float*       __restrict__ out)
{
    const int tid  = threadIdx.x;
    const int warp = tid >> 5;
    const int lane = tid & 31;

    __shared__ float s_loss[B_];

    #pragma unroll
    for (int rep = 0; rep < 2; rep++) {
        const int b = warp + rep * 32;
        const float* cp = childrens + ((size_t)b * J_ + (J_ - 1)) * D_;
        const float* pp = pos       + ((size_t)b * J_ + (J_ - 1)) * D_;

        float4 ca = ((const float4*)cp)[lane];
        float4 cb = ((const float4*)cp)[lane + 32];
        float4 pa = ((const float4*)pp)[lane];
        float4 pb = ((const float4*)pp)[lane + 32];

        float dot = ca.x * pa.x + ca.y * pa.y + ca.z * pa.z + ca.w * pa.w
                  + cb.x * pb.x + cb.y * pb.y + cb.z * pb.z + cb.w * pb.w;
        float cs  = ca.x * ca.x + ca.y * ca.y + ca.z * ca.z + ca.w * ca.w
                  + cb.x * cb.x + cb.y * cb.y + cb.z * cb.z + cb.w * cb.w;
        float ps  = pa.x * pa.x + pa.y * pa.y + pa.z * pa.z + pa.w * pa.w
                  + pb.x * pb.x + pb.y * pb.y + pb.z * pb.z + pb.w * pb.w;
        #pragma unroll
        for (int o = 16; o; o >>= 1) {
            dot += __shfl_xor_sync(0xffffffffu, dot, o);
            cs  += __shfl_xor_sync(0xffffffffu, cs,  o);
            ps  += __shfl_xor_sync(0xffffffffu, ps,  o);
        }
        float pos_sim = dot / (fmaxf(sqrtf(cs), EPS_) * fmaxf(sqrtf(ps), EPS_)) * INV_TEMP;

        // Fold the SPLIT_ block partials for this batch.
        float m = (lane < SPLIT_) ? g_partials[(b * SPLIT_ + lane) * 2 + 0] : -CUDART_INF_F;
        float s = (lane < SPLIT_) ? g_partials[(b * SPLIT_ + lane) * 2 + 1] : 0.0f;
        #pragma unroll
        for (int o = 16; o; o >>= 1) {
            float m2 = __shfl_xor_sync(0xffffffffu, m, o);
            float s2 = __shfl_xor_sync(0xffffffffu, s, o);
            lse_comb(m, s, m2, s2);
        }
        // Include positive logit (always present).
        lse_comb(m, s, pos_sim, 1.0f);
        float lse = m + logf(s);
        if (lane == 0) s_loss[b] = lse - pos_sim;
    }
    __syncthreads();

    // Deterministic tree-sum of the 64 per-batch losses.
    if (tid < 32) {
        float v = s_loss[tid] + s_loss[tid + 32];
        #pragma unroll
        for (int o = 16; o; o >>= 1) v += __shfl_xor_sync(0xffffffffu, v, o);
        if (tid == 0) out[0] = v / (2.0f * (float)B_);
    }
}

// ---------------------------------------------------------------------------
// Launch
// ---------------------------------------------------------------------------
extern "C" void kernel_launch(void* const* d_in, const int* in_sizes, int n_in,
                              void* d_out, int out_size) {
    const float* childrens  = (const float*)d_in[0]; // (B, J, D)
    const float* child_pos  = (const float*)d_in[1]; // (B, J, D)
    const float* child_negs = (const float*)d_in[2]; // (B, K, M, D)
    const int*   gt_labels  = (const int*)d_in[3];   // (B, J)
    const int*   gt_negs    = (const int*)d_in[4];   // (B, K, M)
    float* out = (float*)d_out;

    neg_kernel<<<B_ * SPLIT_, 512>>>(childrens, child_negs, gt_labels, gt_negs);
    final_kernel<<<1, 1024>>>(childrens, child_pos, out);
}

// round 2
// speedup vs baseline: 1.3194x; 1.3194x over previous
#include <cuda_runtime.h>
#include <math_constants.h>

#define B_    64
#define J_    8
#define D_    256
#define NEG_  2048            // K*M
#define SPLIT_ 16             // chunks per batch
#define NPB_  (NEG_/SPLIT_)   // 128 negatives per block
#define NBLOCKS_ (B_*SPLIT_)  // 1024
#define INV_TEMP 10.0f
#define EPS_  1e-8f

// Scratch (no allocation allowed -> device globals; zero-initialized)
__device__ float2       g_part[NBLOCKS_];   // per-block (m, s)
__device__ float        g_pos[B_];          // per-batch pos_sim
__device__ unsigned int g_count;            // arrival counter

__device__ __forceinline__ void lse_comb(float& m, float& s, float m2, float s2) {
    float M = fmaxf(m, m2);
    if (M == -CUDART_INF_F) { m = -CUDART_INF_F; s = 0.0f; return; }
    s = s * __expf(m - M) + s2 * __expf(m2 - M);
    m = M;
}

// ---------------------------------------------------------------------------
// Single fused kernel. 1024 blocks x 128 threads.
// Each warp handles 32 negatives of one (batch, chunk) fully autonomously:
// no block sync on the hot path. chunk-0 blocks also compute pos_sim.
// The last block to arrive folds everything and writes the scalar loss.
// ---------------------------------------------------------------------------
__global__ __launch_bounds__(128) void ntxent_kernel(
    const float* __restrict__ childrens,   // (B, J, D)
    const float* __restrict__ pos,         // (B, J, D)
    const float* __restrict__ negs,        // (B, NEG, D)
    const int*   __restrict__ labels,      // (B, J)
    const int*   __restrict__ neg_labels,  // (B, NEG)
    float*       __restrict__ out)
{
    const int bx    = blockIdx.x;
    const int b     = bx >> 4;             // / SPLIT_
    const int chunk = bx & (SPLIT_ - 1);
    const int tid   = threadIdx.x;
    const int warp  = tid >> 5;
    const int lane  = tid & 31;

    __shared__ float s_m[4], s_s[4];
    __shared__ int   s_last;

    // ---- warp-autonomous: load child, compute its norm in-warp ----
    const float* cp = childrens + ((size_t)b * J_ + (J_ - 1)) * D_;
    const float4 ca = ((const float4*)cp)[lane];        // child[4*lane .. +3]
    const float4 cb = ((const float4*)cp)[lane + 32];   // child[128+4*lane ..]

    float cs = ca.x*ca.x + ca.y*ca.y + ca.z*ca.z + ca.w*ca.w
             + cb.x*cb.x + cb.y*cb.y + cb.z*cb.z + cb.w*cb.w;
    #pragma unroll
    for (int o = 16; o; o >>= 1) cs += __shfl_xor_sync(0xffffffffu, cs, o);
    const float cnorm = fmaxf(sqrtf(cs), EPS_);
    const float invcn = 1.0f / cnorm;

    const int label = __ldg(labels + b * J_ + (J_ - 1));

    // ---- chunk-0 blocks, warp 0: compute pos_sim for this batch ----
    if (chunk == 0 && warp == 0) {
        const float* pp = pos + ((size_t)b * J_ + (J_ - 1)) * D_;
        float4 pa = ((const float4*)pp)[lane];
        float4 pb = ((const float4*)pp)[lane + 32];
        float dot = ca.x*pa.x + ca.y*pa.y + ca.z*pa.z + ca.w*pa.w
                  + cb.x*pb.x + cb.y*pb.y + cb.z*pb.z + cb.w*pb.w;
        float ps  = pa.x*pa.x + pa.y*pa.y + pa.z*pa.z + pa.w*pa.w
                  + pb.x*pb.x + pb.y*pb.y + pb.z*pb.z + pb.w*pb.w;
        #pragma unroll
        for (int o = 16; o; o >>= 1) {
            dot += __shfl_xor_sync(0xffffffffu, dot, o);
            ps  += __shfl_xor_sync(0xffffffffu, ps,  o);
        }
        if (lane == 0)
            g_pos[b] = dot * invcn / fmaxf(sqrtf(ps), EPS_) * INV_TEMP;
    }

    // ---- negatives: 1 label per lane, ballot for matches ----
    const int nbase = chunk * NPB_ + warp * 32;             // this warp's 32 negs
    const int mylab = __ldg(neg_labels + (size_t)b * NEG_ + nbase + lane);
    unsigned int mmask = __ballot_sync(0xffffffffu, mylab == label);

    const float* negbase = negs + ((size_t)b * NEG_ + nbase) * D_;

    float m = -CUDART_INF_F, s = 0.0f;
    while (mmask) {
        const int i = __ffs(mmask) - 1;
        mmask &= mmask - 1;
        const float4* p = (const float4*)(negbase + (size_t)i * D_);
        float4 a = p[lane];
        float4 c = p[lane + 32];
        float dot = a.x*ca.x + a.y*ca.y + a.z*ca.z + a.w*ca.w
                  + c.x*cb.x + c.y*cb.y + c.z*cb.z + c.w*cb.w;
        float ss  = a.x*a.x + a.y*a.y + a.z*a.z + a.w*a.w
                  + c.x*c.x + c.y*c.y + c.z*c.z + c.w*c.w;
        #pragma unroll
        for (int o = 16; o; o >>= 1) {
            dot += __shfl_xor_sync(0xffffffffu, dot, o);
            ss  += __shfl_xor_sync(0xffffffffu, ss,  o);
        }
        float sim = dot * invcn / fmaxf(sqrtf(ss), EPS_) * INV_TEMP;
        float M2  = fmaxf(m, sim);
        s = s * __expf(m - M2) + __expf(sim - M2);
        m = M2;
    }

    if (lane == 0) { s_m[warp] = m; s_s[warp] = s; }
    __syncthreads();

    // ---- warp 0: combine 4 warp partials, publish block partial ----
    if (tid == 0) {
        float mm = s_m[0], sv = s_s[0];
        lse_comb(mm, sv, s_m[1], s_s[1]);
        lse_comb(mm, sv, s_m[2], s_s[2]);
        lse_comb(mm, sv, s_m[3], s_s[3]);
        g_part[bx] = make_float2(mm, sv);
    }

    // ---- arrival: last block finalizes ----
    __threadfence();
    if (tid == 0) {
        unsigned int old = atomicAdd(&g_count, 1u);
        s_last = (old == NBLOCKS_ - 1) ? 1 : 0;
    }
    __syncthreads();
    if (!s_last) return;

    __threadfence();  // acquire: make all blocks' partials visible

    __shared__ float s_loss[B_];
    if (tid < B_) {
        const int batch = tid;
        float m2 = -CUDART_INF_F, s2 = 0.0f;
        #pragma unroll
        for (int k = 0; k < SPLIT_; k++) {
            float2 pr = g_part[batch * SPLIT_ + k];
            lse_comb(m2, s2, pr.x, pr.y);
        }
        const float psim = g_pos[batch];
        lse_comb(m2, s2, psim, 1.0f);
        s_loss[batch] = m2 + logf(s2) - psim;
    }
    __syncthreads();

    if (tid < 32) {
        float v = s_loss[tid] + s_loss[tid + 32];
        #pragma unroll
        for (int o = 16; o; o >>= 1) v += __shfl_xor_sync(0xffffffffu, v, o);
        if (tid == 0) {
            out[0] = v / (2.0f * (float)B_);
            g_count = 0;   // reset for next (graph-replayed) launch
        }
    }
}

extern "C" void kernel_launch(void* const* d_in, const int* in_sizes, int n_in,
                              void* d_out, int out_size) {
    const float* childrens  = (const float*)d_in[0]; // (B, J, D)
    const float* child_pos  = (const float*)d_in[1]; // (B, J, D)
    const float* child_negs = (const float*)d_in[2]; // (B, K, M, D)
    const int*   gt_labels  = (const int*)d_in[3];   // (B, J)
    const int*   gt_negs    = (const int*)d_in[4];   // (B, K, M)
    float* out = (float*)d_out;

    ntxent_kernel<<<NBLOCKS_, 128>>>(childrens, child_pos, child_negs,
                                     gt_labels, gt_negs, out);
}